// round 12
// baseline (speedup 1.0000x reference)
#include <cuda_runtime.h>
#include <cstdint>

// ---------------- problem constants ----------------
#define B_DIM 128
#define H_DIM 101            // 100 hidden + leading 1
#define AV 10201             // 101*101
#define F_DIM 1030301        // 101^3
#define P_DIM 300
#define KT 32                // K per pipeline tile
#define TILES 32197          // ceil(F_DIM / 32)
#define NCTA 148             // K-ranges
#define NTHR 256
#define NH_COLS 150          // N columns per half-CTA
#define NPAD 160             // padded rows in B tile
#define A_BYTES (128 * 64)            // A tile: 128 rows x 64B (fp16, k32)
#define B_BYTES (NPAD * 128)          // B tile: 160 rows x 128B (fp32, k32)
#define STG_BYTES (A_BYTES + B_BYTES) // 28672
#define DYN_SMEM (3 * STG_BYTES)      // 86016 per CTA; x2 CTA/SM = 172KB
#define RPARTS 8

// ---------------- device scratch (no allocs allowed) ----------------
__device__ float g_HA[B_DIM * H_DIM];
__device__ float g_HV[B_DIM * H_DIM];
__device__ float g_HT[B_DIM * H_DIM];
__device__ float g_VT[B_DIM * AV];                               // 5.2 MB, L2-resident
__device__ __align__(16) float g_part[(size_t)NCTA * B_DIM * P_DIM];  // split-K partials
__device__ __align__(16) float g_R4[RPARTS * B_DIM * P_DIM];     // phase-1 reduction
__device__ __align__(16) float g_H[B_DIM * P_DIM];               // relu(fusion@W1^T + b1)

// ---------------- helpers ----------------
__device__ __forceinline__ uint32_t smem_u32(const void* p) {
    uint32_t a;
    asm("{ .reg .u64 t; cvta.to.shared.u64 t, %1; cvt.u32.u64 %0, t; }" : "=r"(a) : "l"(p));
    return a;
}
// pack two fp32 -> f16x2 (hi -> upper half, lo -> lower half)
__device__ __forceinline__ uint32_t cvt2h(float hi, float lo) {
    uint32_t r;
    asm("cvt.rn.f16x2.f32 %0, %1, %2;" : "=r"(r) : "f"(hi), "f"(lo));
    return r;
}
__device__ __forceinline__ void sts128(uint32_t a, uint32_t v0, uint32_t v1,
                                       uint32_t v2, uint32_t v3) {
    asm volatile("st.shared.v4.b32 [%0], {%1,%2,%3,%4};"
                 :: "r"(a), "r"(v0), "r"(v1), "r"(v2), "r"(v3) : "memory");
}
__device__ __forceinline__ void lds128(uint32_t a, uint32_t& v0, uint32_t& v1,
                                       uint32_t& v2, uint32_t& v3) {
    asm volatile("ld.shared.v4.b32 {%0,%1,%2,%3}, [%4];"
                 : "=r"(v0), "=r"(v1), "=r"(v2), "=r"(v3) : "r"(a));
}
__device__ __forceinline__ void cpasync4(uint32_t dst, const float* src) {
    asm volatile("cp.async.ca.shared.global [%0], [%1], 4;" :: "r"(dst), "l"(src) : "memory");
}
__device__ __forceinline__ void cp_commit() {
    asm volatile("cp.async.commit_group;" ::: "memory");
}
__device__ __forceinline__ void cp_wait1() {
    asm volatile("cp.async.wait_group 1;" ::: "memory");
}
// fp16 MMA, m16n8k16, fp32 accumulate
__device__ __forceinline__ void mma_f16(float& d0, float& d1, float& d2, float& d3,
                                        uint32_t a0, uint32_t a1, uint32_t a2, uint32_t a3,
                                        uint32_t b0, uint32_t b1) {
    asm volatile("mma.sync.aligned.m16n8k16.row.col.f32.f16.f16.f32 "
                 "{%0,%1,%2,%3}, {%4,%5,%6,%7}, {%8,%9}, {%0,%1,%2,%3};"
                 : "+f"(d0), "+f"(d1), "+f"(d2), "+f"(d3)
                 : "r"(a0), "r"(a1), "r"(a2), "r"(a3), "r"(b0), "r"(b1));
}

// ---------------- kernel 1: three small encoders ----------------
__global__ void enc_kernel(const float* __restrict__ ax, const float* __restrict__ vx,
                           const float* __restrict__ tx,
                           const float* __restrict__ Wa, const float* __restrict__ ba,
                           const float* __restrict__ Wv, const float* __restrict__ bv,
                           const float* __restrict__ Wt, const float* __restrict__ bt) {
    __shared__ float xs[300];
    int b = blockIdx.x, m = blockIdx.y;
    const float* x    = (m == 0) ? ax : (m == 1) ? vx : tx;
    const float* W    = (m == 0) ? Wa : (m == 1) ? Wv : Wt;
    const float* bias = (m == 0) ? ba : (m == 1) ? bv : bt;
    float* H          = (m == 0) ? g_HA : (m == 1) ? g_HV : g_HT;
    for (int i = threadIdx.x; i < 300; i += blockDim.x) xs[i] = x[b * 300 + i];
    __syncthreads();
    int j = threadIdx.x;
    if (j == 0) H[b * H_DIM] = 1.0f;
    if (j < 100) {
        const float* w = W + j * 300;
        float s = 0.0f;
        #pragma unroll 4
        for (int p = 0; p < 300; p++) s += xs[p] * __ldg(w + p);
        H[b * H_DIM + 1 + j] = s + __ldg(bias + j);
    }
}

// ---------------- kernel 2: VT[b, v*101+t] = _v[b,v] * _t[b,t] ----------------
__global__ void vt_kernel() {
    __shared__ float hv[H_DIM], ht[H_DIM];
    int b = blockIdx.x;
    if (threadIdx.x < H_DIM) {
        hv[threadIdx.x] = g_HV[b * H_DIM + threadIdx.x];
        ht[threadIdx.x] = g_HT[b * H_DIM + threadIdx.x];
    }
    __syncthreads();
    for (int i = threadIdx.x; i < AV; i += 256) {
        int v = i / 101, t = i - v * 101;
        g_VT[b * AV + i] = hv[v] * ht[t];
    }
}

// ---------------- dummy kernel: keeps main_kernel as launch #4 for the ncu window ----------------
__global__ void dummy_kernel() {}

// ---------------- kernel 3: main split-K/split-N GEMM (fp16 m16n8k16) ----------------
// Grid (148, 2): x = K-range, y = N half (150 cols, padded to 160).
// 8 warps, warp grid 2M x 4N, warp tile 64 x 40. 2 CTAs/SM.
// A smem (fp16): 128 rows x 64B, fragment-order per row: byte 16*lc + 8*g + 2*e holds
//   phys k = 16g + 4lc + e; chunk swizzle: chunk ^= (row & 3). One lds128 at chunk lc
//   yields both k16 groups' a-regs for that row: [g0(k0,k1), g0(k2,k3), g1(k0,k1), g1(k2,k3)].
// B smem (fp32): 160 rows x 128B, k contiguous, chunk ^= (row & 1) * 4 (as R11).
// Slot<->phys-k bijection identical on A and B -> exact contraction.
__global__ void __launch_bounds__(NTHR, 2) main_kernel(const float* __restrict__ W1) {
    extern __shared__ char dyn[];
    uint32_t base_s = smem_u32(dyn);

    int tid = threadIdx.x, wid = tid >> 5, lane = tid & 31;
    int cta_k = blockIdx.x;
    int nh = blockIdx.y;
    int wm = wid & 1;          // M half: rows wm*64
    int wn = wid >> 1;         // N block: cols wn*40 (local)
    int lr = lane >> 2;        // 0..7
    int lc = lane & 3;         // 0..3

    // contiguous K-tile range for this K-index
    int q = TILES / NCTA;                  // 217
    int r = TILES - q * NCTA;              // 81
    int t0 = cta_k * q + min(cta_k, r);
    int nt = q + (cta_k < r ? 1 : 0);

    // ---- producer state (rolling) ----
    int kp = t0 * KT;
    int ap = kp / AV;
    int vp = kp - ap * AV;

    // A producer: row = tid>>1, h = tid&1 covers lcp in {2h, 2h+1}
    int arow = tid >> 1;
    int ah   = tid & 1;
    // B producer: warp w loads local row n = bn0 + 8i
    int bn0 = tid >> 5;
    int bw0 = tid & 31;
    const float* Wrow = W1 + (size_t)(nh * NH_COLS + bn0) * F_DIM;
    uint32_t bdst0 = (uint32_t)(bn0 * 128 + (((bw0 >> 2) ^ ((bn0 & 1) * 4)) * 16) + (bw0 & 3) * 4);

    float acc[4][5][4];
    #pragma unroll
    for (int m = 0; m < 4; m++)
        #pragma unroll
        for (int n = 0; n < 5; n++)
            #pragma unroll
            for (int e = 0; e < 4; e++) acc[m][n][e] = 0.0f;

#define PRODUCE(S) do {                                                               \
    uint32_t aB = base_s + (S) * STG_BYTES;                                           \
    uint32_t bB = aB + A_BYTES;                                                       \
    /* ---- A tile: fp16, fragment-order ---- */                                      \
    uint32_t abase = aB + arow * 64;                                                  \
    uint32_t rsw = (uint32_t)(arow & 3);                                              \
    if (vp <= AV - KT && kp + KT <= F_DIM) {  /* fast: 'a' constant over tile */      \
        float ha = g_HA[arow * H_DIM + ap];                                           \
        const float* vrow = g_VT + (size_t)arow * AV + vp;                            \
        _Pragma("unroll")                                                             \
        for (int li = 0; li < 2; li++) {                                              \
            int lcp = 2 * ah + li;                                                    \
            uint32_t p0 = cvt2h(ha * vrow[4 * lcp + 1],      ha * vrow[4 * lcp + 0]); \
            uint32_t p1 = cvt2h(ha * vrow[4 * lcp + 3],      ha * vrow[4 * lcp + 2]); \
            uint32_t p2 = cvt2h(ha * vrow[16 + 4 * lcp + 1], ha * vrow[16 + 4 * lcp + 0]); \
            uint32_t p3 = cvt2h(ha * vrow[16 + 4 * lcp + 3], ha * vrow[16 + 4 * lcp + 2]); \
            sts128(abase + (((uint32_t)lcp ^ rsw) * 16), p0, p1, p2, p3);             \
        }                                                                             \
    } else {                                  /* slow: per-element, division-free */  \
        _Pragma("unroll")                                                             \
        for (int li = 0; li < 2; li++) {                                              \
            int lcp = 2 * ah + li;                                                    \
            float f[8];                                                               \
            _Pragma("unroll")                                                         \
            for (int g = 0; g < 2; g++)                                               \
                _Pragma("unroll")                                                     \
                for (int e = 0; e < 4; e++) {                                         \
                    int off = 16 * g + 4 * lcp + e;                                   \
                    int k = kp + off;                                                 \
                    float val = 0.0f;                                                 \
                    if (k < F_DIM) {                                                  \
                        int vv = vp + off;                                            \
                        int wrap = (vv >= AV);                                        \
                        int a = ap + wrap;                                            \
                        int vt = vv - (wrap ? AV : 0);                                \
                        val = g_HA[arow * H_DIM + a] * g_VT[(size_t)arow * AV + vt];  \
                    }                                                                 \
                    f[g * 4 + e] = val;                                               \
                }                                                                     \
            uint32_t p0 = cvt2h(f[1], f[0]), p1 = cvt2h(f[3], f[2]);                  \
            uint32_t p2 = cvt2h(f[5], f[4]), p3 = cvt2h(f[7], f[6]);                  \
            sts128(abase + (((uint32_t)lcp ^ rsw) * 16), p0, p1, p2, p3);             \
        }                                                                             \
    }                                                                                 \
    /* ---- B tile: 160 rows x 32 words (fp32), rolling pointers ---- */              \
    {                                                                                 \
        int kk = kp + bw0;                                                            \
        const float* src = Wrow + ((kk < F_DIM) ? kk : 0);  /* clamp: A zeros cover */\
        uint32_t dst = bB + bdst0;                                                    \
        _Pragma("unroll")                                                             \
        for (int i = 0; i < 20; i++) {                                                \
            int nl = bn0 + 8 * i;                                                     \
            if (nh == 0 || nl < NH_COLS) cpasync4(dst, src);  /* junk rows skipped */ \
            dst += 8 * 128;                                                           \
            src += (size_t)8 * F_DIM;                                                 \
        }                                                                             \
    }                                                                                 \
    kp += KT; vp += KT; if (vp >= AV) { vp -= AV; ap++; }                             \
} while (0)

    // prologue: produce stages 0,1
    PRODUCE(0); cp_commit();
    PRODUCE(1); cp_commit();

    uint32_t aoff = (uint32_t)((wm * 64 + lr) * 64) + (((uint32_t)lc ^ (uint32_t)(lr & 3)) * 16);
    uint32_t boff = (uint32_t)((wn * 40 + lr) * 128);
    uint32_t bsw  = (uint32_t)(lr & 1) * 4;

    int stage_c = 0, stage_p = 2;
    for (int c = 0; c < nt; c++) {
        cp_wait1();
        __syncthreads();
        if (c + 2 < nt) PRODUCE(stage_p);
        cp_commit();

        uint32_t aB = base_s + stage_c * STG_BYTES;
        uint32_t bB = aB + A_BYTES;

        // A fragments for the whole k32 tile: 8 lds128 -> 32 half2 regs, no cvts
        uint32_t AL[4][4], AH[4][4];
        {
            uint32_t aaddr = aB + aoff;
            #pragma unroll
            for (int m = 0; m < 4; m++) {
                lds128(aaddr,          AL[m][0], AL[m][1], AL[m][2], AL[m][3]);
                lds128(aaddr + 8 * 64, AH[m][0], AH[m][1], AH[m][2], AH[m][3]);
                aaddr += 16 * 64;
            }
        }
        #pragma unroll
        for (int g = 0; g < 2; g++) {
            uint32_t chc = (((uint32_t)(4 * g + lc)) ^ bsw) * 16;
            uint32_t baddr = bB + boff + chc;
            uint32_t bcur[4], bnxt[4];
            lds128(baddr, bcur[0], bcur[1], bcur[2], bcur[3]);
            #pragma unroll
            for (int n = 0; n < 5; n++) {
                if (n < 4) {
                    baddr += 8 * 128;
                    lds128(baddr, bnxt[0], bnxt[1], bnxt[2], bnxt[3]);
                }
                uint32_t b0 = cvt2h(__uint_as_float(bcur[1]), __uint_as_float(bcur[0]));
                uint32_t b1 = cvt2h(__uint_as_float(bcur[3]), __uint_as_float(bcur[2]));
                #pragma unroll
                for (int m = 0; m < 4; m++) {
                    mma_f16(acc[m][n][0], acc[m][n][1], acc[m][n][2], acc[m][n][3],
                            AL[m][2 * g], AH[m][2 * g], AL[m][2 * g + 1], AH[m][2 * g + 1],
                            b0, b1);
                }
                #pragma unroll
                for (int e = 0; e < 4; e++) bcur[e] = bnxt[e];
            }
        }
        stage_c = (stage_c == 2) ? 0 : stage_c + 1;
        stage_p = (stage_p == 2) ? 0 : stage_p + 1;
    }

    // ---- epilogue: deterministic per-K partials; halves write disjoint columns ----
    float* dst = g_part + (size_t)cta_k * B_DIM * P_DIM;
    #pragma unroll
    for (int m = 0; m < 4; m++) {
        int row = wm * 64 + m * 16 + lr;
        #pragma unroll
        for (int n = 0; n < 5; n++) {
            int col_l = wn * 40 + n * 8 + lc * 2;
            if (col_l < NH_COLS) {
                int col = nh * NH_COLS + col_l;
                float2 v0 = make_float2(acc[m][n][0], acc[m][n][1]);
                float2 v1 = make_float2(acc[m][n][2], acc[m][n][3]);
                *reinterpret_cast<float2*>(dst + (size_t)row * P_DIM + col) = v0;
                *reinterpret_cast<float2*>(dst + (size_t)(row + 8) * P_DIM + col) = v1;
            }
        }
    }
#undef PRODUCE
}

// ---------------- kernel 4a: split-K reduce phase 1 (148 -> 8) ----------------
__global__ void reduce1_kernel() {
    const int NG4 = B_DIM * P_DIM / 4;                    // 9600
    int g4 = blockIdx.x * blockDim.x + threadIdx.x;
    if (g4 >= NG4) return;
    int part = blockIdx.y;                                // 0..7
    int c0 = part * 18 + min(part, 4);                    // 148 = 4*19 + 4*18
    int cn = 18 + (part < 4 ? 1 : 0);
    const float4* base = reinterpret_cast<const float4*>(g_part) + (size_t)c0 * NG4 + g4;
    float4 s0 = make_float4(0.f, 0.f, 0.f, 0.f);
    float4 s1 = make_float4(0.f, 0.f, 0.f, 0.f);
    float4 s2 = make_float4(0.f, 0.f, 0.f, 0.f);
    float4 s3 = make_float4(0.f, 0.f, 0.f, 0.f);
    int c = 0;
    #pragma unroll
    for (; c + 4 <= 18; c += 4) {
        float4 v0 = base[(size_t)(c + 0) * NG4];
        float4 v1 = base[(size_t)(c + 1) * NG4];
        float4 v2 = base[(size_t)(c + 2) * NG4];
        float4 v3 = base[(size_t)(c + 3) * NG4];
        s0.x += v0.x; s0.y += v0.y; s0.z += v0.z; s0.w += v0.w;
        s1.x += v1.x; s1.y += v1.y; s1.z += v1.z; s1.w += v1.w;
        s2.x += v2.x; s2.y += v2.y; s2.z += v2.z; s2.w += v2.w;
        s3.x += v3.x; s3.y += v3.y; s3.z += v3.z; s3.w += v3.w;
    }
    for (; c < cn; c++) {
        float4 v0 = base[(size_t)c * NG4];
        s0.x += v0.x; s0.y += v0.y; s0.z += v0.z; s0.w += v0.w;
    }
    float4 o;
    o.x = (s0.x + s1.x) + (s2.x + s3.x);
    o.y = (s0.y + s1.y) + (s2.y + s3.y);
    o.z = (s0.z + s1.z) + (s2.z + s3.z);
    o.w = (s0.w + s1.w) + (s2.w + s3.w);
    reinterpret_cast<float4*>(g_R4)[part * NG4 + g4] = o;
}

// ---------------- kernel 4b: reduce phase 2 + bias + relu ----------------
__global__ void reduce2_kernel(const float* __restrict__ b1) {
    const int NG4 = B_DIM * P_DIM / 4;
    int g4 = blockIdx.x * blockDim.x + threadIdx.x;
    if (g4 >= NG4) return;
    const float4* R = reinterpret_cast<const float4*>(g_R4);
    float sx = 0.f, sy = 0.f, sz = 0.f, sw = 0.f;
    #pragma unroll
    for (int p = 0; p < RPARTS; p++) {
        float4 v = R[p * NG4 + g4];
        sx += v.x; sy += v.y; sz += v.z; sw += v.w;
    }
    int col = (g4 * 4) % P_DIM;
    float4 o;
    o.x = fmaxf(sx + __ldg(b1 + col + 0), 0.f);
    o.y = fmaxf(sy + __ldg(b1 + col + 1), 0.f);
    o.z = fmaxf(sz + __ldg(b1 + col + 2), 0.f);
    o.w = fmaxf(sw + __ldg(b1 + col + 3), 0.f);
    reinterpret_cast<float4*>(g_H)[g4] = o;
}

// ---------------- kernel 5: output layer ----------------
__global__ void out_kernel(const float* __restrict__ W2, const float* __restrict__ b2,
                           float* __restrict__ out) {
    __shared__ float w[P_DIM];
    int o = blockIdx.x;
    for (int i = threadIdx.x; i < P_DIM; i += blockDim.x) w[i] = W2[o * P_DIM + i];
    __syncthreads();
    int b = threadIdx.x;
    if (b < B_DIM) {
        const float* h = g_H + b * P_DIM;
        float s = __ldg(b2 + o);
        #pragma unroll 4
        for (int p = 0; p < P_DIM; p++) s += h[p] * w[p];
        out[b * P_DIM + o] = fmaxf(s, 0.0f);
    }
}

// ---------------- launch ----------------
extern "C" void kernel_launch(void* const* d_in, const int* in_sizes, int n_in,
                              void* d_out, int out_size) {
    const float* ax = (const float*)d_in[0];
    const float* vx = (const float*)d_in[1];
    const float* tx = (const float*)d_in[2];
    const float* Wa = (const float*)d_in[3];
    const float* ba = (const float*)d_in[4];
    const float* Wv = (const float*)d_in[5];
    const float* bv = (const float*)d_in[6];
    const float* Wt = (const float*)d_in[7];
    const float* bt = (const float*)d_in[8];
    const float* W1 = (const float*)d_in[9];
    const float* b1 = (const float*)d_in[10];
    const float* W2 = (const float*)d_in[11];
    const float* b2 = (const float*)d_in[12];
    float* out = (float*)d_out;

    cudaFuncSetAttribute(main_kernel, cudaFuncAttributeMaxDynamicSharedMemorySize, DYN_SMEM);

    enc_kernel<<<dim3(B_DIM, 3), 128>>>(ax, vx, tx, Wa, ba, Wv, bv, Wt, bt);
    vt_kernel<<<B_DIM, 256>>>();
    dummy_kernel<<<1, 32>>>();   // keeps main_kernel as launch #4 for the ncu window
    main_kernel<<<dim3(NCTA, 2), NTHR, DYN_SMEM>>>(W1);
    reduce1_kernel<<<dim3((B_DIM * P_DIM / 4 + 255) / 256, RPARTS), 256>>>();
    reduce2_kernel<<<(B_DIM * P_DIM / 4 + 255) / 256, 256>>>(b1);
    out_kernel<<<P_DIM, 128>>>(W2, b2, out);
}

// round 13
// speedup vs baseline: 1.3105x; 1.3105x over previous
#include <cuda_runtime.h>
#include <cstdint>

// ---------------- problem constants ----------------
#define B_DIM 128
#define H_DIM 101            // 100 hidden + leading 1
#define AV 10201             // 101*101
#define F_DIM 1030301        // 101^3
#define P_DIM 300
#define KT 32                // K per pipeline tile
#define TILES 32197          // ceil(F_DIM / 32)
#define NCTA 148             // K-split
#define NTHR 512
#define A_BYTES (128 * 64)            // A tile: 128 rows x 64B (fp16, k32, granule layout)
#define B_BYTES (320 * 128)           // B tile: 320 rows x 128B (fp32; rows>=300 junk)
#define STG_BYTES (A_BYTES + B_BYTES) // 49152
#define DYN_SMEM (3 * STG_BYTES)      // 147456 (1 CTA of 512 thr per SM)
#define RPARTS 8

// ---------------- device scratch (no allocs allowed) ----------------
__device__ float g_HA[B_DIM * H_DIM];
__device__ float g_HV[B_DIM * H_DIM];
__device__ float g_HT[B_DIM * H_DIM];
__device__ float g_VT[B_DIM * AV];                               // 5.2 MB, L2-resident
__device__ __align__(16) float g_part[(size_t)NCTA * B_DIM * P_DIM];  // split-K partials
__device__ __align__(16) float g_R4[RPARTS * B_DIM * P_DIM];     // phase-1 reduction
__device__ __align__(16) float g_H[B_DIM * P_DIM];               // relu(fusion@W1^T + b1)

// ---------------- helpers ----------------
__device__ __forceinline__ uint32_t smem_u32(const void* p) {
    uint32_t a;
    asm("{ .reg .u64 t; cvta.to.shared.u64 t, %1; cvt.u32.u64 %0, t; }" : "=r"(a) : "l"(p));
    return a;
}
// pack two fp32 -> f16x2 (first arg -> upper half, second -> lower half)
__device__ __forceinline__ uint32_t cvt2h(float hi, float lo) {
    uint32_t r;
    asm("cvt.rn.f16x2.f32 %0, %1, %2;" : "=r"(r) : "f"(hi), "f"(lo));
    return r;
}
__device__ __forceinline__ void sts64(uint32_t a, uint32_t v0, uint32_t v1) {
    asm volatile("st.shared.v2.b32 [%0], {%1,%2};" :: "r"(a), "r"(v0), "r"(v1) : "memory");
}
__device__ __forceinline__ void lds64(uint32_t a, uint32_t& v0, uint32_t& v1) {
    asm volatile("ld.shared.v2.b32 {%0,%1}, [%2];" : "=r"(v0), "=r"(v1) : "r"(a));
}
__device__ __forceinline__ void lds128(uint32_t a, uint32_t& v0, uint32_t& v1,
                                       uint32_t& v2, uint32_t& v3) {
    asm volatile("ld.shared.v4.b32 {%0,%1,%2,%3}, [%4];"
                 : "=r"(v0), "=r"(v1), "=r"(v2), "=r"(v3) : "r"(a));
}
__device__ __forceinline__ void cpasync4(uint32_t dst, const float* src) {
    asm volatile("cp.async.ca.shared.global [%0], [%1], 4;" :: "r"(dst), "l"(src) : "memory");
}
__device__ __forceinline__ void cp_commit() {
    asm volatile("cp.async.commit_group;" ::: "memory");
}
__device__ __forceinline__ void cp_wait1() {
    asm volatile("cp.async.wait_group 1;" ::: "memory");
}
// fp16 MMA, m16n8k16, fp32 accumulate
__device__ __forceinline__ void mma_f16(float& d0, float& d1, float& d2, float& d3,
                                        uint32_t a0, uint32_t a1, uint32_t a2, uint32_t a3,
                                        uint32_t b0, uint32_t b1) {
    asm volatile("mma.sync.aligned.m16n8k16.row.col.f32.f16.f16.f32 "
                 "{%0,%1,%2,%3}, {%4,%5,%6,%7}, {%8,%9}, {%0,%1,%2,%3};"
                 : "+f"(d0), "+f"(d1), "+f"(d2), "+f"(d3)
                 : "r"(a0), "r"(a1), "r"(a2), "r"(a3), "r"(b0), "r"(b1));
}

// ---------------- kernel 1: three small encoders ----------------
__global__ void enc_kernel(const float* __restrict__ ax, const float* __restrict__ vx,
                           const float* __restrict__ tx,
                           const float* __restrict__ Wa, const float* __restrict__ ba,
                           const float* __restrict__ Wv, const float* __restrict__ bv,
                           const float* __restrict__ Wt, const float* __restrict__ bt) {
    __shared__ float xs[300];
    int b = blockIdx.x, m = blockIdx.y;
    const float* x    = (m == 0) ? ax : (m == 1) ? vx : tx;
    const float* W    = (m == 0) ? Wa : (m == 1) ? Wv : Wt;
    const float* bias = (m == 0) ? ba : (m == 1) ? bv : bt;
    float* H          = (m == 0) ? g_HA : (m == 1) ? g_HV : g_HT;
    for (int i = threadIdx.x; i < 300; i += blockDim.x) xs[i] = x[b * 300 + i];
    __syncthreads();
    int j = threadIdx.x;
    if (j == 0) H[b * H_DIM] = 1.0f;
    if (j < 100) {
        const float* w = W + j * 300;
        float s = 0.0f;
        #pragma unroll 4
        for (int p = 0; p < 300; p++) s += xs[p] * __ldg(w + p);
        H[b * H_DIM + 1 + j] = s + __ldg(bias + j);
    }
}

// ---------------- kernel 2: VT[b, v*101+t] = _v[b,v] * _t[b,t] ----------------
__global__ void vt_kernel() {
    __shared__ float hv[H_DIM], ht[H_DIM];
    int b = blockIdx.x;
    if (threadIdx.x < H_DIM) {
        hv[threadIdx.x] = g_HV[b * H_DIM + threadIdx.x];
        ht[threadIdx.x] = g_HT[b * H_DIM + threadIdx.x];
    }
    __syncthreads();
    for (int i = threadIdx.x; i < AV; i += 256) {
        int v = i / 101, t = i - v * 101;
        g_VT[b * AV + i] = hv[v] * ht[t];
    }
}

// ---------------- dummy kernel: keeps main_kernel as launch #4 for the ncu window ----------------
__global__ void dummy_kernel() {}

// ---------------- kernel 3: main split-K GEMM (512 thr, fp16 m16n8k16) ----------------
// Grid 148 (K-split). 16 warps, warp grid 2M x 8N, warp tile 64 x 40. acc = 80 regs.
// A smem: fp16, per row 64B = 8 granules of 8B; granule(g,c) at index ((g<<2)|c) ^ ((row&2)<<1);
//   granule holds phys k = 16g+4c+{0,1} (bytes 0-3) and 16g+4c+{2,3} (bytes 4-7).
//   Consumer lds64 -> a-regs direct (slots {2lc,2lc+1} = .x, {2lc+8,2lc+9} = .y). Conflict-free.
// B smem: fp32, row 128B, k contiguous, 16B chunk ^ ((row&1)*4)  (R11 layout, proven).
// Identical slot<->phys-k bijection on A and B -> exact contraction.
__global__ void __launch_bounds__(NTHR, 1) main_kernel(const float* __restrict__ W1) {
    extern __shared__ char dyn[];
    uint32_t base_s = smem_u32(dyn);

    int tid = threadIdx.x, wid = tid >> 5, lane = tid & 31;
    int cta = blockIdx.x;
    int wm = wid & 1;          // M half: rows wm*64
    int wn = wid >> 1;         // N block: cols wn*40 (0..7)
    int lr = lane >> 2;        // 0..7
    int lc = lane & 3;         // 0..3

    // contiguous K-tile range for this CTA
    int q = TILES / NCTA;                  // 217
    int r = TILES - q * NCTA;              // 81
    int t0 = cta * q + min(cta, r);
    int nt = q + (cta < r ? 1 : 0);

    // ---- producer state (rolling) ----
    int kp = t0 * KT;
    int ap = kp / AV;
    int vp = kp - ap * AV;

    // A producer: row = tid>>2 (0..127), lcp = tid&3
    int arow = tid >> 2;
    int lcp  = tid & 3;
    uint32_t sA = (uint32_t)(arow & 2) << 1;
    uint32_t ag0 = ((uint32_t)lcp ^ sA) * 8;          // granule byte offset, g=0
    uint32_t ag1 = ((uint32_t)(4 | lcp) ^ sA) * 8;    // g=1
    // B producer: warp w loads row bn0 + 16i
    int bn0 = tid >> 5;
    int bw0 = tid & 31;
    const float* Wrow = W1 + (size_t)bn0 * F_DIM;
    uint32_t bdst0 = (uint32_t)(bn0 * 128 + (((bw0 >> 2) ^ ((bn0 & 1) * 4)) * 16) + (bw0 & 3) * 4);

    float acc[4][5][4];
    #pragma unroll
    for (int m = 0; m < 4; m++)
        #pragma unroll
        for (int n = 0; n < 5; n++)
            #pragma unroll
            for (int e = 0; e < 4; e++) acc[m][n][e] = 0.0f;

#define PRODUCE(S) do {                                                               \
    uint32_t aB = base_s + (S) * STG_BYTES;                                           \
    uint32_t bB = aB + A_BYTES;                                                       \
    /* ---- A tile: fp16 granule layout, 2 sts64 per thread ---- */                   \
    uint32_t abase = aB + arow * 64;                                                  \
    if (vp <= AV - KT && kp + KT <= F_DIM) {  /* fast: 'a' constant over tile */      \
        float ha = g_HA[arow * H_DIM + ap];                                           \
        const float* vrow = g_VT + (size_t)arow * AV + vp;                            \
        float v0 = ha * vrow[4 * lcp + 0], v1 = ha * vrow[4 * lcp + 1];               \
        float v2 = ha * vrow[4 * lcp + 2], v3 = ha * vrow[4 * lcp + 3];               \
        float w0 = ha * vrow[16 + 4 * lcp + 0], w1 = ha * vrow[16 + 4 * lcp + 1];     \
        float w2 = ha * vrow[16 + 4 * lcp + 2], w3 = ha * vrow[16 + 4 * lcp + 3];     \
        sts64(abase + ag0, cvt2h(v1, v0), cvt2h(v3, v2));                             \
        sts64(abase + ag1, cvt2h(w1, w0), cvt2h(w3, w2));                             \
    } else {                                  /* slow: per-element, division-free */  \
        float f[8];                                                                   \
        _Pragma("unroll")                                                             \
        for (int g = 0; g < 2; g++)                                                   \
            _Pragma("unroll")                                                         \
            for (int e = 0; e < 4; e++) {                                             \
                int off = 16 * g + 4 * lcp + e;                                       \
                int k = kp + off;                                                     \
                float val = 0.0f;                                                     \
                if (k < F_DIM) {                                                      \
                    int vv = vp + off;                                                \
                    int wrap = (vv >= AV);                                            \
                    int a = ap + wrap;                                                \
                    int vt = vv - (wrap ? AV : 0);                                    \
                    val = g_HA[arow * H_DIM + a] * g_VT[(size_t)arow * AV + vt];      \
                }                                                                     \
                f[g * 4 + e] = val;                                                   \
            }                                                                         \
        sts64(abase + ag0, cvt2h(f[1], f[0]), cvt2h(f[3], f[2]));                     \
        sts64(abase + ag1, cvt2h(f[5], f[4]), cvt2h(f[7], f[6]));                     \
    }                                                                                 \
    /* ---- B tile: 300 rows x 32 words (fp32), rolling pointers ---- */              \
    {                                                                                 \
        int kk = kp + bw0;                                                            \
        const float* src = Wrow + ((kk < F_DIM) ? kk : 0);  /* clamp: A zeros cover */\
        uint32_t dst = bB + bdst0;                                                    \
        _Pragma("unroll")                                                             \
        for (int i = 0; i < 18; i++) {                                                \
            cpasync4(dst, src);                                                       \
            dst += 16 * 128;                                                          \
            src += (size_t)16 * F_DIM;                                                \
        }                                                                             \
        if (bn0 < 12) cpasync4(dst, src);  /* rows 288..299 */                        \
    }                                                                                 \
    kp += KT; vp += KT; if (vp >= AV) { vp -= AV; ap++; }                             \
} while (0)

    // prologue: produce stages 0,1
    PRODUCE(0); cp_commit();
    PRODUCE(1); cp_commit();

    // consumer constants
    uint32_t arow0 = (uint32_t)(wm * 64 + lr);                       // A row base
    uint32_t sAc   = (uint32_t)(lr & 2) << 1;                        // A consumer swizzle
    uint32_t brow0 = (uint32_t)(wn * 40 + lr);                       // B row base
    uint32_t sBc   = (uint32_t)(lr & 1) << 2;                        // B consumer swizzle

    int stage_c = 0, stage_p = 2;
    for (int c = 0; c < nt; c++) {
        cp_wait1();
        __syncthreads();
        if (c + 2 < nt) PRODUCE(stage_p);
        cp_commit();

        uint32_t aB = base_s + stage_c * STG_BYTES;
        uint32_t bB = aB + A_BYTES;

        #pragma unroll
        for (int g = 0; g < 2; g++) {
            uint32_t agr = (((uint32_t)(g * 4 + lc)) ^ sAc) * 8;
            // A fragments for this g: 8 lds64 -> 16 regs, no cvts
            uint32_t Alo[4][2], Ahi[4][2];
            {
                uint32_t aaddr = aB + arow0 * 64 + agr;
                #pragma unroll
                for (int m = 0; m < 4; m++) {
                    lds64(aaddr,       Alo[m][0], Alo[m][1]);
                    lds64(aaddr + 512, Ahi[m][0], Ahi[m][1]);   // row +8
                    aaddr += 16 * 64;
                }
            }
            uint32_t bchunk = (((uint32_t)(g * 4 + lc)) ^ sBc) * 16;
            uint32_t baddr = bB + brow0 * 128 + bchunk;
            #pragma unroll
            for (int n = 0; n < 5; n++) {
                uint32_t bw[4];
                lds128(baddr, bw[0], bw[1], bw[2], bw[3]);
                baddr += 8 * 128;
                uint32_t b0 = cvt2h(__uint_as_float(bw[1]), __uint_as_float(bw[0]));
                uint32_t b1 = cvt2h(__uint_as_float(bw[3]), __uint_as_float(bw[2]));
                #pragma unroll
                for (int m = 0; m < 4; m++) {
                    mma_f16(acc[m][n][0], acc[m][n][1], acc[m][n][2], acc[m][n][3],
                            Alo[m][0], Ahi[m][0], Alo[m][1], Ahi[m][1], b0, b1);
                }
            }
        }
        stage_c = (stage_c == 2) ? 0 : stage_c + 1;
        stage_p = (stage_p == 2) ? 0 : stage_p + 1;
    }

    // ---- epilogue: deterministic per-CTA partials ----
    float* dst = g_part + (size_t)cta * B_DIM * P_DIM;
    #pragma unroll
    for (int m = 0; m < 4; m++) {
        int row = wm * 64 + m * 16 + lr;
        #pragma unroll
        for (int n = 0; n < 5; n++) {
            int col = wn * 40 + n * 8 + lc * 2;
            if (col < 300) {
                float2 v0 = make_float2(acc[m][n][0], acc[m][n][1]);
                float2 v1 = make_float2(acc[m][n][2], acc[m][n][3]);
                *reinterpret_cast<float2*>(dst + (size_t)row * P_DIM + col) = v0;
                *reinterpret_cast<float2*>(dst + (size_t)(row + 8) * P_DIM + col) = v1;
            }
        }
    }
#undef PRODUCE
}

// ---------------- kernel 4a: split-K reduce phase 1 (148 -> 8) ----------------
__global__ void reduce1_kernel() {
    const int NG4 = B_DIM * P_DIM / 4;                    // 9600
    int g4 = blockIdx.x * blockDim.x + threadIdx.x;
    if (g4 >= NG4) return;
    int part = blockIdx.y;                                // 0..7
    int c0 = part * 18 + min(part, 4);                    // 148 = 4*19 + 4*18
    int cn = 18 + (part < 4 ? 1 : 0);
    const float4* base = reinterpret_cast<const float4*>(g_part) + (size_t)c0 * NG4 + g4;
    float4 s0 = make_float4(0.f, 0.f, 0.f, 0.f);
    float4 s1 = make_float4(0.f, 0.f, 0.f, 0.f);
    float4 s2 = make_float4(0.f, 0.f, 0.f, 0.f);
    float4 s3 = make_float4(0.f, 0.f, 0.f, 0.f);
    int c = 0;
    #pragma unroll
    for (; c + 4 <= 18; c += 4) {
        float4 v0 = base[(size_t)(c + 0) * NG4];
        float4 v1 = base[(size_t)(c + 1) * NG4];
        float4 v2 = base[(size_t)(c + 2) * NG4];
        float4 v3 = base[(size_t)(c + 3) * NG4];
        s0.x += v0.x; s0.y += v0.y; s0.z += v0.z; s0.w += v0.w;
        s1.x += v1.x; s1.y += v1.y; s1.z += v1.z; s1.w += v1.w;
        s2.x += v2.x; s2.y += v2.y; s2.z += v2.z; s2.w += v2.w;
        s3.x += v3.x; s3.y += v3.y; s3.z += v3.z; s3.w += v3.w;
    }
    for (; c < cn; c++) {
        float4 v0 = base[(size_t)c * NG4];
        s0.x += v0.x; s0.y += v0.y; s0.z += v0.z; s0.w += v0.w;
    }
    float4 o;
    o.x = (s0.x + s1.x) + (s2.x + s3.x);
    o.y = (s0.y + s1.y) + (s2.y + s3.y);
    o.z = (s0.z + s1.z) + (s2.z + s3.z);
    o.w = (s0.w + s1.w) + (s2.w + s3.w);
    reinterpret_cast<float4*>(g_R4)[part * NG4 + g4] = o;
}

// ---------------- kernel 4b: reduce phase 2 + bias + relu ----------------
__global__ void reduce2_kernel(const float* __restrict__ b1) {
    const int NG4 = B_DIM * P_DIM / 4;
    int g4 = blockIdx.x * blockDim.x + threadIdx.x;
    if (g4 >= NG4) return;
    const float4* R = reinterpret_cast<const float4*>(g_R4);
    float sx = 0.f, sy = 0.f, sz = 0.f, sw = 0.f;
    #pragma unroll
    for (int p = 0; p < RPARTS; p++) {
        float4 v = R[p * NG4 + g4];
        sx += v.x; sy += v.y; sz += v.z; sw += v.w;
    }
    int col = (g4 * 4) % P_DIM;
    float4 o;
    o.x = fmaxf(sx + __ldg(b1 + col + 0), 0.f);
    o.y = fmaxf(sy + __ldg(b1 + col + 1), 0.f);
    o.z = fmaxf(sz + __ldg(b1 + col + 2), 0.f);
    o.w = fmaxf(sw + __ldg(b1 + col + 3), 0.f);
    reinterpret_cast<float4*>(g_H)[g4] = o;
}

// ---------------- kernel 5: output layer ----------------
__global__ void out_kernel(const float* __restrict__ W2, const float* __restrict__ b2,
                           float* __restrict__ out) {
    __shared__ float w[P_DIM];
    int o = blockIdx.x;
    for (int i = threadIdx.x; i < P_DIM; i += blockDim.x) w[i] = W2[o * P_DIM + i];
    __syncthreads();
    int b = threadIdx.x;
    if (b < B_DIM) {
        const float* h = g_H + b * P_DIM;
        float s = __ldg(b2 + o);
        #pragma unroll 4
        for (int p = 0; p < P_DIM; p++) s += h[p] * w[p];
        out[b * P_DIM + o] = fmaxf(s, 0.0f);
    }
}

// ---------------- launch ----------------
extern "C" void kernel_launch(void* const* d_in, const int* in_sizes, int n_in,
                              void* d_out, int out_size) {
    const float* ax = (const float*)d_in[0];
    const float* vx = (const float*)d_in[1];
    const float* tx = (const float*)d_in[2];
    const float* Wa = (const float*)d_in[3];
    const float* ba = (const float*)d_in[4];
    const float* Wv = (const float*)d_in[5];
    const float* bv = (const float*)d_in[6];
    const float* Wt = (const float*)d_in[7];
    const float* bt = (const float*)d_in[8];
    const float* W1 = (const float*)d_in[9];
    const float* b1 = (const float*)d_in[10];
    const float* W2 = (const float*)d_in[11];
    const float* b2 = (const float*)d_in[12];
    float* out = (float*)d_out;

    cudaFuncSetAttribute(main_kernel, cudaFuncAttributeMaxDynamicSharedMemorySize, DYN_SMEM);

    enc_kernel<<<dim3(B_DIM, 3), 128>>>(ax, vx, tx, Wa, ba, Wv, bv, Wt, bt);
    vt_kernel<<<B_DIM, 256>>>();
    dummy_kernel<<<1, 32>>>();   // keeps main_kernel as launch #4 for the ncu window
    main_kernel<<<NCTA, NTHR, DYN_SMEM>>>(W1);
    reduce1_kernel<<<dim3((B_DIM * P_DIM / 4 + 255) / 256, RPARTS), 256>>>();
    reduce2_kernel<<<(B_DIM * P_DIM / 4 + 255) / 256, 256>>>(b1);
    out_kernel<<<P_DIM, 128>>>(W2, b2, out);
}

// round 14
// speedup vs baseline: 1.3140x; 1.0027x over previous
#include <cuda_runtime.h>
#include <cstdint>

// ---------------- problem constants ----------------
#define B_DIM 128
#define H_DIM 101            // 100 hidden + leading 1
#define AV 10201             // 101*101
#define F_DIM 1030301        // 101^3
#define P_DIM 300
#define KT 64                // K per pipeline tile
#define TILES 16099          // ceil(F_DIM / 64), last tile has 29 valid k
#define NCTA 148             // K-split
#define NTHR 512
#define A_BYTES (128 * 128)           // A tile: 128 rows x 128B (fp16, k64, granule layout)
#define B_BYTES (320 * 256)           // B tile: 320 rows x 256B (fp32; rows>=300 junk)
#define STG_BYTES (A_BYTES + B_BYTES) // 98304
#define DYN_SMEM (2 * STG_BYTES)      // 196608 (1 CTA of 512 thr per SM)
#define RPARTS 8

// ---------------- device scratch (no allocs allowed) ----------------
__device__ float g_HA[B_DIM * H_DIM];
__device__ float g_HV[B_DIM * H_DIM];
__device__ float g_HT[B_DIM * H_DIM];
__device__ float g_VT[B_DIM * AV];                               // 5.2 MB, L2-resident
__device__ __align__(16) float g_part[(size_t)NCTA * B_DIM * P_DIM];  // split-K partials
__device__ __align__(16) float g_R4[RPARTS * B_DIM * P_DIM];     // phase-1 reduction
__device__ __align__(16) float g_H[B_DIM * P_DIM];               // relu(fusion@W1^T + b1)

// ---------------- helpers ----------------
__device__ __forceinline__ uint32_t smem_u32(const void* p) {
    uint32_t a;
    asm("{ .reg .u64 t; cvta.to.shared.u64 t, %1; cvt.u32.u64 %0, t; }" : "=r"(a) : "l"(p));
    return a;
}
// pack two fp32 -> f16x2 (first arg -> upper half, second -> lower half)
__device__ __forceinline__ uint32_t cvt2h(float hi, float lo) {
    uint32_t r;
    asm("cvt.rn.f16x2.f32 %0, %1, %2;" : "=r"(r) : "f"(hi), "f"(lo));
    return r;
}
__device__ __forceinline__ void sts64(uint32_t a, uint32_t v0, uint32_t v1) {
    asm volatile("st.shared.v2.b32 [%0], {%1,%2};" :: "r"(a), "r"(v0), "r"(v1) : "memory");
}
__device__ __forceinline__ void lds64(uint32_t a, uint32_t& v0, uint32_t& v1) {
    asm volatile("ld.shared.v2.b32 {%0,%1}, [%2];" : "=r"(v0), "=r"(v1) : "r"(a));
}
__device__ __forceinline__ void lds128(uint32_t a, uint32_t& v0, uint32_t& v1,
                                       uint32_t& v2, uint32_t& v3) {
    asm volatile("ld.shared.v4.b32 {%0,%1,%2,%3}, [%4];"
                 : "=r"(v0), "=r"(v1), "=r"(v2), "=r"(v3) : "r"(a));
}
__device__ __forceinline__ void cpasync4(uint32_t dst, const float* src) {
    asm volatile("cp.async.ca.shared.global [%0], [%1], 4;" :: "r"(dst), "l"(src) : "memory");
}
__device__ __forceinline__ void cp_commit() {
    asm volatile("cp.async.commit_group;" ::: "memory");
}
__device__ __forceinline__ void cp_wait0() {
    asm volatile("cp.async.wait_group 0;" ::: "memory");
}
// fp16 MMA, m16n8k16, fp32 accumulate
__device__ __forceinline__ void mma_f16(float& d0, float& d1, float& d2, float& d3,
                                        uint32_t a0, uint32_t a1, uint32_t a2, uint32_t a3,
                                        uint32_t b0, uint32_t b1) {
    asm volatile("mma.sync.aligned.m16n8k16.row.col.f32.f16.f16.f32 "
                 "{%0,%1,%2,%3}, {%4,%5,%6,%7}, {%8,%9}, {%0,%1,%2,%3};"
                 : "+f"(d0), "+f"(d1), "+f"(d2), "+f"(d3)
                 : "r"(a0), "r"(a1), "r"(a2), "r"(a3), "r"(b0), "r"(b1));
}

// ---------------- kernel 1: three small encoders ----------------
__global__ void enc_kernel(const float* __restrict__ ax, const float* __restrict__ vx,
                           const float* __restrict__ tx,
                           const float* __restrict__ Wa, const float* __restrict__ ba,
                           const float* __restrict__ Wv, const float* __restrict__ bv,
                           const float* __restrict__ Wt, const float* __restrict__ bt) {
    __shared__ float xs[300];
    int b = blockIdx.x, m = blockIdx.y;
    const float* x    = (m == 0) ? ax : (m == 1) ? vx : tx;
    const float* W    = (m == 0) ? Wa : (m == 1) ? Wv : Wt;
    const float* bias = (m == 0) ? ba : (m == 1) ? bv : bt;
    float* H          = (m == 0) ? g_HA : (m == 1) ? g_HV : g_HT;
    for (int i = threadIdx.x; i < 300; i += blockDim.x) xs[i] = x[b * 300 + i];
    __syncthreads();
    int j = threadIdx.x;
    if (j == 0) H[b * H_DIM] = 1.0f;
    if (j < 100) {
        const float* w = W + j * 300;
        float s = 0.0f;
        #pragma unroll 4
        for (int p = 0; p < 300; p++) s += xs[p] * __ldg(w + p);
        H[b * H_DIM + 1 + j] = s + __ldg(bias + j);
    }
}

// ---------------- kernel 2: VT[b, v*101+t] = _v[b,v] * _t[b,t] ----------------
__global__ void vt_kernel() {
    __shared__ float hv[H_DIM], ht[H_DIM];
    int b = blockIdx.x;
    if (threadIdx.x < H_DIM) {
        hv[threadIdx.x] = g_HV[b * H_DIM + threadIdx.x];
        ht[threadIdx.x] = g_HT[b * H_DIM + threadIdx.x];
    }
    __syncthreads();
    for (int i = threadIdx.x; i < AV; i += 256) {
        int v = i / 101, t = i - v * 101;
        g_VT[b * AV + i] = hv[v] * ht[t];
    }
}

// ---------------- dummy kernel: keeps main_kernel as launch #4 for the ncu window ----------------
__global__ void dummy_kernel() {}

// ---------------- kernel 3: main split-K GEMM (512 thr, fp16 m16n8k16, KT=64) ----------------
// Grid 148 (K-split). 16 warps, warp grid 2M x 8N, warp tile 64 x 40. acc = 80 regs.
// A smem: fp16, row = 128B = 16 granules of 8B. Granule(g,c) stored at index
//   ((g ^ (row&3)) << 2) | c  — rows are 128B (bank-aligned), so this gives exactly
//   2 lanes per granule in every lds64/sts64 wavefront pair (minimum, conflict-free).
//   Granule holds phys k = 16g+4c+{0,1} (lo b32) and +{2,3} (hi b32).
// B smem: fp32, row = 256B = 16 chunks of 16B, k contiguous, chunk ^ ((row&1)*4).
// Identical slot<->phys-k bijection on A and B per row -> exact contraction.
__global__ void __launch_bounds__(NTHR, 1) main_kernel(const float* __restrict__ W1) {
    extern __shared__ char dyn[];
    uint32_t base_s = smem_u32(dyn);

    int tid = threadIdx.x, wid = tid >> 5, lane = tid & 31;
    int cta = blockIdx.x;
    int wm = wid & 1;          // M half: rows wm*64
    int wn = wid >> 1;         // N block: cols wn*40 (0..7)
    int lr = lane >> 2;        // 0..7
    int lc = lane & 3;         // 0..3

    // contiguous K-tile range for this CTA
    int q = TILES / NCTA;                  // 108
    int r = TILES - q * NCTA;              // 115
    int t0 = cta * q + min(cta, r);
    int nt = q + (cta < r ? 1 : 0);

    // ---- producer state (rolling) ----
    int kp = t0 * KT;
    int ap = kp / AV;
    int vp = kp - ap * AV;

    // A producer: row = tid>>2 (0..127), lcp = tid&3; 4 granules (g=0..3)
    int arow = tid >> 2;
    int lcp  = tid & 3;
    uint32_t rs3 = (uint32_t)(arow & 3);
    // B producer: warp w covers rows bn0+16i; thread covers words bw0 and bw0+32
    int bn0 = tid >> 5;
    int bw0 = tid & 31;
    const float* Wrow = W1 + (size_t)bn0 * F_DIM;
    uint32_t bdst0 = (uint32_t)(bn0 * 256 + (((bw0 >> 2) ^ ((bn0 & 1) * 4)) * 16) + (bw0 & 3) * 4);

    float acc[4][5][4];
    #pragma unroll
    for (int m = 0; m < 4; m++)
        #pragma unroll
        for (int n = 0; n < 5; n++)
            #pragma unroll
            for (int e = 0; e < 4; e++) acc[m][n][e] = 0.0f;

#define PRODUCE(S) do {                                                               \
    uint32_t aB = base_s + (S) * STG_BYTES;                                           \
    uint32_t bB = aB + A_BYTES;                                                       \
    /* ---- A tile: fp16 granule layout, 4 sts64 per thread ---- */                   \
    uint32_t abase = aB + arow * 128;                                                 \
    if (vp <= AV - KT && kp + KT <= F_DIM) {  /* fast: 'a' constant over tile */      \
        float ha = g_HA[arow * H_DIM + ap];                                           \
        const float* vrow = g_VT + (size_t)arow * AV + vp + 4 * lcp;                  \
        _Pragma("unroll")                                                             \
        for (int g = 0; g < 4; g++) {                                                 \
            float v0 = ha * vrow[16 * g + 0], v1 = ha * vrow[16 * g + 1];             \
            float v2 = ha * vrow[16 * g + 2], v3 = ha * vrow[16 * g + 3];             \
            uint32_t gran = (((uint32_t)g ^ rs3) << 2) | (uint32_t)lcp;               \
            sts64(abase + gran * 8, cvt2h(v1, v0), cvt2h(v3, v2));                    \
        }                                                                             \
    } else {                                  /* slow: per-element, division-free */  \
        _Pragma("unroll")                                                             \
        for (int g = 0; g < 4; g++) {                                                 \
            float f[4];                                                               \
            _Pragma("unroll")                                                         \
            for (int e = 0; e < 4; e++) {                                             \
                int off = 16 * g + 4 * lcp + e;                                       \
                int k = kp + off;                                                     \
                float val = 0.0f;                                                     \
                if (k < F_DIM) {                                                      \
                    int vv = vp + off;                                                \
                    int wrap = (vv >= AV);                                            \
                    int a = ap + wrap;                                                \
                    int vt = vv - (wrap ? AV : 0);                                    \
                    val = g_HA[arow * H_DIM + a] * g_VT[(size_t)arow * AV + vt];      \
                }                                                                     \
                f[e] = val;                                                           \
            }                                                                         \
            uint32_t gran = (((uint32_t)g ^ rs3) << 2) | (uint32_t)lcp;               \
            sts64(abase + gran * 8, cvt2h(f[1], f[0]), cvt2h(f[3], f[2]));            \
        }                                                                             \
    }                                                                                 \
    /* ---- B tile: 300 rows x 64 words (fp32), 2 word-columns per thread ---- */     \
    {                                                                                 \
        int kk0 = kp + bw0;                                                           \
        int kk1 = kk0 + 32;                                                           \
        const float* s0 = Wrow + ((kk0 < F_DIM) ? kk0 : 0);  /* clamp: A zeros cover */\
        const float* s1 = Wrow + ((kk1 < F_DIM) ? kk1 : 0);                           \
        uint32_t dst = bB + bdst0;                                                    \
        _Pragma("unroll")                                                             \
        for (int i = 0; i < 18; i++) {                                                \
            cpasync4(dst, s0);                                                        \
            cpasync4(dst + 128, s1);                                                  \
            dst += 16 * 256;                                                          \
            s0 += (size_t)16 * F_DIM;                                                 \
            s1 += (size_t)16 * F_DIM;                                                 \
        }                                                                             \
        if (bn0 < 12) { cpasync4(dst, s0); cpasync4(dst + 128, s1); }                 \
    }                                                                                 \
    kp += KT; vp += KT; if (vp >= AV) { vp -= AV; ap++; }                             \
} while (0)

    // prologue: produce stage 0
    PRODUCE(0); cp_commit();

    // consumer constants
    uint32_t arow0 = (uint32_t)(wm * 64 + lr);                       // A row base
    uint32_t sA3   = (uint32_t)(lr & 3);                             // A consumer swizzle (row&3)
    uint32_t brow0 = (uint32_t)(wn * 40 + lr);                       // B row base
    uint32_t sBc   = (uint32_t)(lr & 1) << 2;                        // B consumer swizzle

    int stage = 0;
    for (int c = 0; c < nt; c++) {
        cp_wait0();
        __syncthreads();
        if (c + 1 < nt) { PRODUCE(1 - stage); cp_commit(); }

        uint32_t aB = base_s + stage * STG_BYTES;
        uint32_t bB = aB + A_BYTES;

        #pragma unroll
        for (int g = 0; g < 4; g++) {
            uint32_t agr = (((((uint32_t)g) ^ sA3) << 2) | (uint32_t)lc) * 8;
            // A fragments for this g: 8 lds64 -> 16 regs, no cvts
            uint32_t Alo[4][2], Ahi[4][2];
            {
                uint32_t aaddr = aB + arow0 * 128 + agr;
                #pragma unroll
                for (int m = 0; m < 4; m++) {
                    lds64(aaddr,        Alo[m][0], Alo[m][1]);
                    lds64(aaddr + 1024, Ahi[m][0], Ahi[m][1]);   // row +8
                    aaddr += 16 * 128;
                }
            }
            uint32_t bchunk = (((uint32_t)(g * 4 + lc)) ^ sBc) * 16;
            uint32_t baddr = bB + brow0 * 256 + bchunk;
            #pragma unroll
            for (int n = 0; n < 5; n++) {
                uint32_t bw[4];
                lds128(baddr, bw[0], bw[1], bw[2], bw[3]);
                baddr += 8 * 256;
                uint32_t b0 = cvt2h(__uint_as_float(bw[1]), __uint_as_float(bw[0]));
                uint32_t b1 = cvt2h(__uint_as_float(bw[3]), __uint_as_float(bw[2]));
                #pragma unroll
                for (int m = 0; m < 4; m++) {
                    mma_f16(acc[m][n][0], acc[m][n][1], acc[m][n][2], acc[m][n][3],
                            Alo[m][0], Ahi[m][0], Alo[m][1], Ahi[m][1], b0, b1);
                }
            }
        }
        stage ^= 1;
    }

    // ---- epilogue: deterministic per-CTA partials ----
    float* dst = g_part + (size_t)cta * B_DIM * P_DIM;
    #pragma unroll
    for (int m = 0; m < 4; m++) {
        int row = wm * 64 + m * 16 + lr;
        #pragma unroll
        for (int n = 0; n < 5; n++) {
            int col = wn * 40 + n * 8 + lc * 2;
            if (col < 300) {
                float2 v0 = make_float2(acc[m][n][0], acc[m][n][1]);
                float2 v1 = make_float2(acc[m][n][2], acc[m][n][3]);
                *reinterpret_cast<float2*>(dst + (size_t)row * P_DIM + col) = v0;
                *reinterpret_cast<float2*>(dst + (size_t)(row + 8) * P_DIM + col) = v1;
            }
        }
    }
#undef PRODUCE
}

// ---------------- kernel 4a: split-K reduce phase 1 (148 -> 8) ----------------
__global__ void reduce1_kernel() {
    const int NG4 = B_DIM * P_DIM / 4;                    // 9600
    int g4 = blockIdx.x * blockDim.x + threadIdx.x;
    if (g4 >= NG4) return;
    int part = blockIdx.y;                                // 0..7
    int c0 = part * 18 + min(part, 4);                    // 148 = 4*19 + 4*18
    int cn = 18 + (part < 4 ? 1 : 0);
    const float4* base = reinterpret_cast<const float4*>(g_part) + (size_t)c0 * NG4 + g4;
    float4 s0 = make_float4(0.f, 0.f, 0.f, 0.f);
    float4 s1 = make_float4(0.f, 0.f, 0.f, 0.f);
    float4 s2 = make_float4(0.f, 0.f, 0.f, 0.f);
    float4 s3 = make_float4(0.f, 0.f, 0.f, 0.f);
    int c = 0;
    #pragma unroll
    for (; c + 4 <= 18; c += 4) {
        float4 v0 = base[(size_t)(c + 0) * NG4];
        float4 v1 = base[(size_t)(c + 1) * NG4];
        float4 v2 = base[(size_t)(c + 2) * NG4];
        float4 v3 = base[(size_t)(c + 3) * NG4];
        s0.x += v0.x; s0.y += v0.y; s0.z += v0.z; s0.w += v0.w;
        s1.x += v1.x; s1.y += v1.y; s1.z += v1.z; s1.w += v1.w;
        s2.x += v2.x; s2.y += v2.y; s2.z += v2.z; s2.w += v2.w;
        s3.x += v3.x; s3.y += v3.y; s3.z += v3.z; s3.w += v3.w;
    }
    for (; c < cn; c++) {
        float4 v0 = base[(size_t)c * NG4];
        s0.x += v0.x; s0.y += v0.y; s0.z += v0.z; s0.w += v0.w;
    }
    float4 o;
    o.x = (s0.x + s1.x) + (s2.x + s3.x);
    o.y = (s0.y + s1.y) + (s2.y + s3.y);
    o.z = (s0.z + s1.z) + (s2.z + s3.z);
    o.w = (s0.w + s1.w) + (s2.w + s3.w);
    reinterpret_cast<float4*>(g_R4)[part * NG4 + g4] = o;
}

// ---------------- kernel 4b: reduce phase 2 + bias + relu ----------------
__global__ void reduce2_kernel(const float* __restrict__ b1) {
    const int NG4 = B_DIM * P_DIM / 4;
    int g4 = blockIdx.x * blockDim.x + threadIdx.x;
    if (g4 >= NG4) return;
    const float4* R = reinterpret_cast<const float4*>(g_R4);
    float sx = 0.f, sy = 0.f, sz = 0.f, sw = 0.f;
    #pragma unroll
    for (int p = 0; p < RPARTS; p++) {
        float4 v = R[p * NG4 + g4];
        sx += v.x; sy += v.y; sz += v.z; sw += v.w;
    }
    int col = (g4 * 4) % P_DIM;
    float4 o;
    o.x = fmaxf(sx + __ldg(b1 + col + 0), 0.f);
    o.y = fmaxf(sy + __ldg(b1 + col + 1), 0.f);
    o.z = fmaxf(sz + __ldg(b1 + col + 2), 0.f);
    o.w = fmaxf(sw + __ldg(b1 + col + 3), 0.f);
    reinterpret_cast<float4*>(g_H)[g4] = o;
}

// ---------------- kernel 5: output layer ----------------
__global__ void out_kernel(const float* __restrict__ W2, const float* __restrict__ b2,
                           float* __restrict__ out) {
    __shared__ float w[P_DIM];
    int o = blockIdx.x;
    for (int i = threadIdx.x; i < P_DIM; i += blockDim.x) w[i] = W2[o * P_DIM + i];
    __syncthreads();
    int b = threadIdx.x;
    if (b < B_DIM) {
        const float* h = g_H + b * P_DIM;
        float s = __ldg(b2 + o);
        #pragma unroll 4
        for (int p = 0; p < P_DIM; p++) s += h[p] * w[p];
        out[b * P_DIM + o] = fmaxf(s, 0.0f);
    }
}

// ---------------- launch ----------------
extern "C" void kernel_launch(void* const* d_in, const int* in_sizes, int n_in,
                              void* d_out, int out_size) {
    const float* ax = (const float*)d_in[0];
    const float* vx = (const float*)d_in[1];
    const float* tx = (const float*)d_in[2];
    const float* Wa = (const float*)d_in[3];
    const float* ba = (const float*)d_in[4];
    const float* Wv = (const float*)d_in[5];
    const float* bv = (const float*)d_in[6];
    const float* Wt = (const float*)d_in[7];
    const float* bt = (const float*)d_in[8];
    const float* W1 = (const float*)d_in[9];
    const float* b1 = (const float*)d_in[10];
    const float* W2 = (const float*)d_in[11];
    const float* b2 = (const float*)d_in[12];
    float* out = (float*)d_out;

    cudaFuncSetAttribute(main_kernel, cudaFuncAttributeMaxDynamicSharedMemorySize, DYN_SMEM);

    enc_kernel<<<dim3(B_DIM, 3), 128>>>(ax, vx, tx, Wa, ba, Wv, bv, Wt, bt);
    vt_kernel<<<B_DIM, 256>>>();
    dummy_kernel<<<1, 32>>>();   // keeps main_kernel as launch #4 for the ncu window
    main_kernel<<<NCTA, NTHR, DYN_SMEM>>>(W1);
    reduce1_kernel<<<dim3((B_DIM * P_DIM / 4 + 255) / 256, RPARTS), 256>>>();
    reduce2_kernel<<<(B_DIM * P_DIM / 4 + 255) / 256, 256>>>(b1);
    out_kernel<<<P_DIM, 128>>>(W2, b2, out);
}